// round 4
// baseline (speedup 1.0000x reference)
#include <cuda_runtime.h>
#include <math.h>

// Problem constants
#define NB   2
#define SEQ  1024           // P == C == 1024
#define EMB  1024           // E == H == 1024
#define NHD  16             // num heads
#define HDD  64             // head dim == head_out_dim
#define NROWS (NB*SEQ)      // 2048

// ---------------- scratch (device globals; no allocations allowed) ----------
__device__ float g_Qh[NB*NHD*SEQ*HDD];          // 8 MB, head-major [bh][i][d]
__device__ float g_Kh[NB*NHD*SEQ*HDD];
__device__ float g_Vh[NB*NHD*SEQ*HDD];
__device__ float g_S [NB*NHD*SEQ*SEQ];          // 128 MB scores/probs
__device__ float g_tmp[NROWS*EMB];              // attn out / mlp out
__device__ float g_x1 [NROWS*EMB];
__device__ float g_x2 [NROWS*EMB];
__device__ float g_hid[NROWS*EMB];

// ---------------------------------------------------------------------------
// Generic GEMM: C = A[M,K] @ W[K,N] + bias, 64x64 tile, 4x4 per thread.
// mode 0: plain row-major out
// mode 1: relu(out)
// mode 2: head-major scatter: out[((b*16 + n%16)*SEQ + i)*64 + n/16]
// M,N multiples of 64; K multiple of 16.
// ---------------------------------------------------------------------------
__global__ void gemm_bias_k(const float* __restrict__ A,
                            const float* __restrict__ W,
                            const float* __restrict__ bias,
                            float* __restrict__ C,
                            int M, int N, int K, int mode)
{
    __shared__ float As[16][64];   // [kk][i]
    __shared__ float Ws[16][64];   // [kk][j]
    const int tx = threadIdx.x, ty = threadIdx.y;
    const int t  = ty * 16 + tx;
    const int rowBase = blockIdx.y * 64;
    const int colBase = blockIdx.x * 64;

    const int ai = t >> 2;            // 0..63  (A row within tile)
    const int ak = (t & 3) * 4;       // 0,4,8,12
    const int wk = t >> 4;            // 0..15
    const int wj = (t & 15) * 4;      // 0..60

    const float* Aptr = A + (size_t)(rowBase + ai) * K + ak;
    const float* Wptr = W + (size_t)wk * N + colBase + wj;

    float acc[4][4] = {};

    for (int k0 = 0; k0 < K; k0 += 16) {
        float4 av = *(const float4*)(Aptr + k0);
        float4 wv = *(const float4*)(Wptr + (size_t)k0 * N);
        As[ak+0][ai] = av.x; As[ak+1][ai] = av.y;
        As[ak+2][ai] = av.z; As[ak+3][ai] = av.w;
        *(float4*)&Ws[wk][wj] = wv;
        __syncthreads();
        #pragma unroll
        for (int kk = 0; kk < 16; kk++) {
            float4 a4 = *(const float4*)&As[kk][ty*4];
            float4 b4 = *(const float4*)&Ws[kk][tx*4];
            float a_[4] = {a4.x, a4.y, a4.z, a4.w};
            float b_[4] = {b4.x, b4.y, b4.z, b4.w};
            #pragma unroll
            for (int m = 0; m < 4; m++)
                #pragma unroll
                for (int n = 0; n < 4; n++)
                    acc[m][n] += a_[m] * b_[n];
        }
        __syncthreads();
    }

    #pragma unroll
    for (int m = 0; m < 4; m++) {
        const int row = rowBase + ty*4 + m;
        #pragma unroll
        for (int n = 0; n < 4; n++) {
            const int col = colBase + tx*4 + n;
            float v = acc[m][n] + bias[col];
            if (mode == 1) v = fmaxf(v, 0.f);
            if (mode == 2) {
                const int b = row >> 10, i = row & 1023;
                const int h = col & 15,  d = col >> 4;
                C[(((size_t)(b*NHD + h) * SEQ) + i) * HDD + d] = v;
            } else {
                C[(size_t)row * N + col] = v;
            }
        }
    }
}

// ---------------------------------------------------------------------------
// QK^T per (b,h): S[bh][i][j] = 0.125 * sum_d Q[bh][i][d]*K[bh][j][d]
// ---------------------------------------------------------------------------
__global__ void qk_k(const float* __restrict__ Q,
                     const float* __restrict__ Kh,
                     float* __restrict__ S)
{
    __shared__ float Qs[16][64];   // [kk][i]
    __shared__ float Ks[16][64];   // [kk][j]
    const int tx = threadIdx.x, ty = threadIdx.y;
    const int t  = ty * 16 + tx;
    const int bh = blockIdx.z;
    const int iBase = blockIdx.y * 64;
    const int jBase = blockIdx.x * 64;

    const float* Qb = Q  + (size_t)bh * SEQ * HDD;
    const float* Kb = Kh + (size_t)bh * SEQ * HDD;

    const int li = t >> 2;
    const int lk = (t & 3) * 4;

    float acc[4][4] = {};

    for (int k0 = 0; k0 < HDD; k0 += 16) {
        float4 qv = *(const float4*)(Qb + (size_t)(iBase + li) * HDD + k0 + lk);
        float4 kv = *(const float4*)(Kb + (size_t)(jBase + li) * HDD + k0 + lk);
        Qs[lk+0][li] = qv.x; Qs[lk+1][li] = qv.y; Qs[lk+2][li] = qv.z; Qs[lk+3][li] = qv.w;
        Ks[lk+0][li] = kv.x; Ks[lk+1][li] = kv.y; Ks[lk+2][li] = kv.z; Ks[lk+3][li] = kv.w;
        __syncthreads();
        #pragma unroll
        for (int kk = 0; kk < 16; kk++) {
            float4 a4 = *(const float4*)&Qs[kk][ty*4];
            float4 b4 = *(const float4*)&Ks[kk][tx*4];
            float a_[4] = {a4.x, a4.y, a4.z, a4.w};
            float b_[4] = {b4.x, b4.y, b4.z, b4.w};
            #pragma unroll
            for (int m = 0; m < 4; m++)
                #pragma unroll
                for (int n = 0; n < 4; n++)
                    acc[m][n] += a_[m] * b_[n];
        }
        __syncthreads();
    }

    float* Srow = S + (size_t)bh * SEQ * SEQ;
    #pragma unroll
    for (int m = 0; m < 4; m++)
        #pragma unroll
        for (int n = 0; n < 4; n++)
            Srow[(size_t)(iBase + ty*4 + m) * SEQ + jBase + tx*4 + n] = acc[m][n] * 0.125f;
}

// ---------------------------------------------------------------------------
// Row softmax over j, then p += mask1 (+ mask2).  In-place on S.
// One block per (bh, i) row; 256 threads, 4 elems/thread (cols = 1024).
// ---------------------------------------------------------------------------
__global__ void softmax_mask_k(float* __restrict__ S,
                               const float* __restrict__ m1,
                               const float* __restrict__ m2)
{
    __shared__ float red[256];
    const int r   = blockIdx.x;          // bh*SEQ + i
    const int bh  = r >> 10;
    const int i   = r & 1023;
    const int b   = bh >> 4;
    const int tid = threadIdx.x;

    float* row = S + (size_t)r * SEQ;
    const float* mr1 = m1 + ((size_t)b * SEQ + i) * SEQ;
    const float* mr2 = m2 ? m2 + ((size_t)b * SEQ + i) * SEQ : nullptr;

    float v[4];
    #pragma unroll
    for (int c = 0; c < 4; c++) v[c] = row[tid + c*256];

    float mx = fmaxf(fmaxf(v[0], v[1]), fmaxf(v[2], v[3]));
    red[tid] = mx; __syncthreads();
    for (int s = 128; s > 0; s >>= 1) {
        if (tid < s) red[tid] = fmaxf(red[tid], red[tid + s]);
        __syncthreads();
    }
    mx = red[0]; __syncthreads();

    float e[4], sum = 0.f;
    #pragma unroll
    for (int c = 0; c < 4; c++) { e[c] = expf(v[c] - mx); sum += e[c]; }
    red[tid] = sum; __syncthreads();
    for (int s = 128; s > 0; s >>= 1) {
        if (tid < s) red[tid] += red[tid + s];
        __syncthreads();
    }
    const float inv = 1.f / red[0];

    #pragma unroll
    for (int c = 0; c < 4; c++) {
        const int j = tid + c*256;
        float p = e[c] * inv + mr1[j];
        if (mr2) p += mr2[j];
        row[j] = p;
    }
}

// ---------------------------------------------------------------------------
// P @ V per (b,h): out[i][o] = sum_j P[bh][i][j] * V[bh][j][o]
// Scatter to interleaved layout: dst[(b*SEQ+i)*EMB + o*16 + h]
// ---------------------------------------------------------------------------
__global__ void pv_k(const float* __restrict__ P,
                     const float* __restrict__ V,
                     float* __restrict__ dst)
{
    __shared__ float Ps[16][64];   // [kk][i]
    __shared__ float Vs[16][64];   // [kk][o]
    const int tx = threadIdx.x, ty = threadIdx.y;
    const int t  = ty * 16 + tx;
    const int bh = blockIdx.z;
    const int iBase = blockIdx.y * 64;

    const float* Pb = P + (size_t)bh * SEQ * SEQ;
    const float* Vb = V + (size_t)bh * SEQ * HDD;

    const int ai = t >> 2;
    const int ak = (t & 3) * 4;
    const int wk = t >> 4;
    const int wj = (t & 15) * 4;

    float acc[4][4] = {};

    for (int k0 = 0; k0 < SEQ; k0 += 16) {
        float4 pv = *(const float4*)(Pb + (size_t)(iBase + ai) * SEQ + k0 + ak);
        float4 vv = *(const float4*)(Vb + (size_t)(k0 + wk) * HDD + wj);
        Ps[ak+0][ai] = pv.x; Ps[ak+1][ai] = pv.y; Ps[ak+2][ai] = pv.z; Ps[ak+3][ai] = pv.w;
        *(float4*)&Vs[wk][wj] = vv;
        __syncthreads();
        #pragma unroll
        for (int kk = 0; kk < 16; kk++) {
            float4 a4 = *(const float4*)&Ps[kk][ty*4];
            float4 b4 = *(const float4*)&Vs[kk][tx*4];
            float a_[4] = {a4.x, a4.y, a4.z, a4.w};
            float b_[4] = {b4.x, b4.y, b4.z, b4.w};
            #pragma unroll
            for (int m = 0; m < 4; m++)
                #pragma unroll
                for (int n = 0; n < 4; n++)
                    acc[m][n] += a_[m] * b_[n];
        }
        __syncthreads();
    }

    const int b = bh >> 4, h = bh & 15;
    #pragma unroll
    for (int m = 0; m < 4; m++) {
        const int i = iBase + ty*4 + m;
        #pragma unroll
        for (int n = 0; n < 4; n++) {
            const int o = tx*4 + n;
            dst[((size_t)(b*SEQ + i)) * EMB + o*NHD + h] = acc[m][n];
        }
    }
}

// ---------------------------------------------------------------------------
// out = LayerNorm(X_row)*g + b + res_row   (eps 1e-5, over EMB=1024)
// ---------------------------------------------------------------------------
__global__ void ln_res_k(const float* __restrict__ X,
                         const float* __restrict__ res,
                         const float* __restrict__ gam,
                         const float* __restrict__ bet,
                         float* __restrict__ out)
{
    __shared__ float red[256];
    const int r   = blockIdx.x;
    const int tid = threadIdx.x;
    const float* xr = X   + (size_t)r * EMB;
    const float* rr = res + (size_t)r * EMB;
    float* orow     = out + (size_t)r * EMB;

    float v[4];
    #pragma unroll
    for (int c = 0; c < 4; c++) v[c] = xr[tid + c*256];

    float s = v[0] + v[1] + v[2] + v[3];
    red[tid] = s; __syncthreads();
    for (int k = 128; k > 0; k >>= 1) {
        if (tid < k) red[tid] += red[tid + k];
        __syncthreads();
    }
    const float mean = red[0] * (1.f / EMB); __syncthreads();

    float sq = 0.f;
    #pragma unroll
    for (int c = 0; c < 4; c++) { float d = v[c] - mean; sq += d * d; }
    red[tid] = sq; __syncthreads();
    for (int k = 128; k > 0; k >>= 1) {
        if (tid < k) red[tid] += red[tid + k];
        __syncthreads();
    }
    const float rstd = rsqrtf(red[0] * (1.f / EMB) + 1e-5f);

    #pragma unroll
    for (int c = 0; c < 4; c++) {
        const int j = tid + c*256;
        orow[j] = (v[c] - mean) * rstd * gam[j] + bet[j] + rr[j];
    }
}

// ---------------------------------------------------------------------------
extern "C" void kernel_launch(void* const* d_in, const int* in_sizes, int n_in,
                              void* d_out, int out_size)
{
    (void)in_sizes; (void)n_in; (void)out_size;

    const float* x      = (const float*)d_in[0];
    const float* ctx    = (const float*)d_in[1];
    const float* causal = (const float*)d_in[2];
    const float* ppad   = (const float*)d_in[3];
    const float* cpad   = (const float*)d_in[4];
    const float* sa_Wq  = (const float*)d_in[5];
    const float* sa_bq  = (const float*)d_in[6];
    const float* sa_Wk  = (const float*)d_in[7];
    const float* sa_bk  = (const float*)d_in[8];
    const float* sa_Wv  = (const float*)d_in[9];
    const float* sa_bv  = (const float*)d_in[10];
    const float* ca_Wq  = (const float*)d_in[11];
    const float* ca_bq  = (const float*)d_in[12];
    const float* ca_Wk  = (const float*)d_in[13];
    const float* ca_bk  = (const float*)d_in[14];
    const float* ca_Wv  = (const float*)d_in[15];
    const float* ca_bv  = (const float*)d_in[16];
    const float* ln1_g  = (const float*)d_in[17];
    const float* ln1_b  = (const float*)d_in[18];
    const float* ln2_g  = (const float*)d_in[19];
    const float* ln2_b  = (const float*)d_in[20];
    const float* ln3_g  = (const float*)d_in[21];
    const float* ln3_b  = (const float*)d_in[22];
    const float* mlp_W1 = (const float*)d_in[23];
    const float* mlp_b1 = (const float*)d_in[24];
    const float* mlp_W2 = (const float*)d_in[25];
    const float* mlp_b2 = (const float*)d_in[26];
    float* out = (float*)d_out;

    float *Qh, *Kh, *Vh, *S, *tmp, *x1, *x2, *hid;
    cudaGetSymbolAddress((void**)&Qh,  g_Qh);
    cudaGetSymbolAddress((void**)&Kh,  g_Kh);
    cudaGetSymbolAddress((void**)&Vh,  g_Vh);
    cudaGetSymbolAddress((void**)&S,   g_S);
    cudaGetSymbolAddress((void**)&tmp, g_tmp);
    cudaGetSymbolAddress((void**)&x1,  g_x1);
    cudaGetSymbolAddress((void**)&x2,  g_x2);
    cudaGetSymbolAddress((void**)&hid, g_hid);

    const dim3 tb(16, 16);
    const dim3 gProj(EMB/64, NROWS/64);         // (16, 32)
    const dim3 gQK(SEQ/64, SEQ/64, NB*NHD);     // (16, 16, 32)
    const dim3 gPV(1, SEQ/64, NB*NHD);          // (1, 16, 32)

    // ---- self-attention ----
    gemm_bias_k<<<gProj, tb>>>(x, sa_Wq, sa_bq, Qh, NROWS, EMB, EMB, 2);
    gemm_bias_k<<<gProj, tb>>>(x, sa_Wk, sa_bk, Kh, NROWS, EMB, EMB, 2);
    gemm_bias_k<<<gProj, tb>>>(x, sa_Wv, sa_bv, Vh, NROWS, EMB, EMB, 2);
    qk_k<<<gQK, tb>>>(Qh, Kh, S);
    softmax_mask_k<<<NB*NHD*SEQ, 256>>>(S, causal, ppad);
    pv_k<<<gPV, tb>>>(S, Vh, tmp);
    ln_res_k<<<NROWS, 256>>>(tmp, x, ln1_g, ln1_b, x1);

    // ---- cross-attention ----
    gemm_bias_k<<<gProj, tb>>>(x1,  ca_Wq, ca_bq, Qh, NROWS, EMB, EMB, 2);
    gemm_bias_k<<<gProj, tb>>>(ctx, ca_Wk, ca_bk, Kh, NROWS, EMB, EMB, 2);
    gemm_bias_k<<<gProj, tb>>>(ctx, ca_Wv, ca_bv, Vh, NROWS, EMB, EMB, 2);
    qk_k<<<gQK, tb>>>(Qh, Kh, S);
    softmax_mask_k<<<NB*NHD*SEQ, 256>>>(S, cpad, nullptr);
    pv_k<<<gPV, tb>>>(S, Vh, tmp);
    ln_res_k<<<NROWS, 256>>>(tmp, x1, ln2_g, ln2_b, x2);

    // ---- MLP ----
    gemm_bias_k<<<gProj, tb>>>(x2,  mlp_W1, mlp_b1, hid, NROWS, EMB, EMB, 1);
    gemm_bias_k<<<gProj, tb>>>(hid, mlp_W2, mlp_b2, tmp, NROWS, EMB, EMB, 0);
    ln_res_k<<<NROWS, 256>>>(tmp, x2, ln3_g, ln3_b, out);
}

// round 5
// speedup vs baseline: 1.8331x; 1.8331x over previous
#include <cuda_runtime.h>
#include <math.h>
#include <stdint.h>

// Problem constants
#define NB   2
#define SEQ  1024           // P == C == 1024
#define EMB  1024           // E == H == 1024
#define NHD  16             // num heads
#define HDD  64             // head dim == head_out_dim
#define NROWS (NB*SEQ)      // 2048

// ---------------- scratch (device globals; no allocations allowed) ----------
__device__ float g_Qh[NB*NHD*SEQ*HDD];          // 8 MB, head-major [bh][i][d]
__device__ float g_Kh[NB*NHD*SEQ*HDD];
__device__ float g_Vh[NB*NHD*SEQ*HDD];
__device__ float g_S [NB*NHD*SEQ*SEQ];          // 128 MB scores/probs
__device__ float g_tmp[NROWS*EMB];
__device__ float g_x1 [NROWS*EMB];
__device__ float g_x2 [NROWS*EMB];
__device__ float g_hid[NROWS*EMB];

// round f32 -> tf32 (RNA) kept in f32 container
__device__ __forceinline__ float cvt_tf32(float x) {
    uint32_t u;
    asm("cvt.rna.tf32.f32 %0, %1;" : "=r"(u) : "f"(x));
    return __uint_as_float(u);
}

// ---------------------------------------------------------------------------
// tf32 tensor-core GEMM.  C = A[M,K] @ B[K,N] (B optionally given as [N,K]).
// BM=128 fixed, BK=32 fixed, 256 threads, 8 warps (WARPS_M x WARPS_N).
// MODE 0: C[r*1024+c] = acc + bias[c]
// MODE 1: relu(acc + bias[c])
// MODE 2: head-scatter: C[((b*16 + c%16)*1024 + i)*64 + c/16] = acc + bias[c]
// MODE 3: scores: C[z*1M + r*1024 + c] = acc * 0.125
// MODE 4: pv interleave: C[(b*1024 + r)*1024 + c*16 + h] = acc   (b=z>>4,h=z&15)
// ---------------------------------------------------------------------------
template<int BN, int WARPS_M, int WARPS_N, bool BTRANS, int MODE>
__global__ void __launch_bounds__(256, 2)
tf32gemm(const float* __restrict__ A, const float* __restrict__ Bg,
         const float* __restrict__ bias, float* __restrict__ C,
         int K, int lda, int ldb, size_t astride, size_t bstride)
{
    constexpr int BM  = 128, BK = 32;
    constexpr int SMA = BM + 8;
    constexpr int SNB = BN + 8;
    constexpr int WMT = BM / WARPS_M;
    constexpr int WNT = BN / WARPS_N;
    constexpr int MF  = WMT / 16;
    constexpr int NF  = WNT / 8;
    static_assert(WARPS_M * WARPS_N == 8, "8 warps");
    static_assert(!BTRANS || BN == 128, "trans loader assumes BN=128");

    extern __shared__ float sm[];
    float* As = sm;                    // [2][BK][SMA]
    float* Bs = sm + 2 * BK * SMA;     // [2][BK][SNB]

    const int tid  = threadIdx.x;
    const int lane = tid & 31;
    const int wid  = tid >> 5;
    const int g    = lane >> 2;        // group id 0..7
    const int tig  = lane & 3;         // thread-in-group 0..3
    const int wrow = wid / WARPS_N;
    const int wcol = wid % WARPS_N;

    const int z  = blockIdx.z;
    const int m0 = blockIdx.y * BM;
    const int n0 = blockIdx.x * BN;
    const float* Ab = A  + (size_t)z * astride;
    const float* Bb = Bg + (size_t)z * bstride;

    float acc[MF][NF][4];
    #pragma unroll
    for (int i = 0; i < MF; i++)
        #pragma unroll
        for (int j = 0; j < NF; j++)
            #pragma unroll
            for (int q = 0; q < 4; q++) acc[i][j][q] = 0.f;

    const int am    = tid & 127;       // row (or B-row for trans) within tile
    const int ahalf = tid >> 7;        // which 16-float half of the 32-K chunk

    auto loadA = [&](int k0, int buf) {
        // A row-major [m][k] -> As[k][m]  (transpose store, conflict-free)
        const float* src = Ab + (size_t)(m0 + am) * lda + k0 + ahalf * 16;
        float* dst = As + buf * (BK * SMA) + (ahalf * 16) * SMA + am;
        #pragma unroll
        for (int i = 0; i < 4; i++) {
            float4 v = *(const float4*)(src + 4 * i);
            dst[(4*i+0)*SMA] = cvt_tf32(v.x);
            dst[(4*i+1)*SMA] = cvt_tf32(v.y);
            dst[(4*i+2)*SMA] = cvt_tf32(v.z);
            dst[(4*i+3)*SMA] = cvt_tf32(v.w);
        }
    };
    auto loadB = [&](int k0, int buf) {
        if constexpr (BTRANS) {
            // Bg is [N][K] row-major (e.g. K-matrix [j][d]) -> Bs[k][n]
            const float* src = Bb + (size_t)(n0 + am) * ldb + k0 + ahalf * 16;
            float* dst = Bs + buf * (BK * SNB) + (ahalf * 16) * SNB + am;
            #pragma unroll
            for (int i = 0; i < 4; i++) {
                float4 v = *(const float4*)(src + 4 * i);
                dst[(4*i+0)*SNB] = cvt_tf32(v.x);
                dst[(4*i+1)*SNB] = cvt_tf32(v.y);
                dst[(4*i+2)*SNB] = cvt_tf32(v.z);
                dst[(4*i+3)*SNB] = cvt_tf32(v.w);
            }
        } else {
            // Bg row-major [K][N] -> Bs[k][n], vectorized
            constexpr int NV  = BN / 4;
            constexpr int TOT = BK * NV;
            #pragma unroll
            for (int it = 0; it < TOT / 256; it++) {
                int t = it * 256 + tid;
                int k = t / NV, nq = t % NV;
                float4 v = *(const float4*)(Bb + (size_t)(k0 + k) * ldb + n0 + nq * 4);
                float4 w;
                w.x = cvt_tf32(v.x); w.y = cvt_tf32(v.y);
                w.z = cvt_tf32(v.z); w.w = cvt_tf32(v.w);
                *(float4*)(Bs + buf * (BK * SNB) + k * SNB + nq * 4) = w;
            }
        }
    };

    loadA(0, 0); loadB(0, 0);
    __syncthreads();

    const int KT = K / BK;
    for (int kt = 0; kt < KT; kt++) {
        const int cur = kt & 1;
        if (kt + 1 < KT) { loadA((kt + 1) * BK, cur ^ 1); loadB((kt + 1) * BK, cur ^ 1); }

        const float* Ac = As + cur * (BK * SMA) + wrow * WMT;
        const float* Bc = Bs + cur * (BK * SNB) + wcol * WNT;
        #pragma unroll
        for (int ks = 0; ks < 4; ks++) {
            const int kk = ks * 8;
            uint32_t af[MF][4], bf[NF][2];
            #pragma unroll
            for (int fm = 0; fm < MF; fm++) {
                const float* p = Ac + (kk + tig) * SMA + fm * 16 + g;
                af[fm][0] = __float_as_uint(p[0]);
                af[fm][1] = __float_as_uint(p[8]);
                af[fm][2] = __float_as_uint(p[4 * SMA]);
                af[fm][3] = __float_as_uint(p[4 * SMA + 8]);
            }
            #pragma unroll
            for (int fn = 0; fn < NF; fn++) {
                const float* p = Bc + (kk + tig) * SNB + fn * 8 + g;
                bf[fn][0] = __float_as_uint(p[0]);
                bf[fn][1] = __float_as_uint(p[4 * SNB]);
            }
            #pragma unroll
            for (int fm = 0; fm < MF; fm++)
                #pragma unroll
                for (int fn = 0; fn < NF; fn++)
                    asm volatile(
                        "mma.sync.aligned.m16n8k8.row.col.f32.tf32.tf32.f32 "
                        "{%0,%1,%2,%3}, {%4,%5,%6,%7}, {%8,%9}, {%0,%1,%2,%3};"
                        : "+f"(acc[fm][fn][0]), "+f"(acc[fm][fn][1]),
                          "+f"(acc[fm][fn][2]), "+f"(acc[fm][fn][3])
                        : "r"(af[fm][0]), "r"(af[fm][1]),
                          "r"(af[fm][2]), "r"(af[fm][3]),
                          "r"(bf[fn][0]), "r"(bf[fn][1]));
        }
        __syncthreads();
    }

    // ----------------------------- epilogue --------------------------------
    const int rowBase = m0 + wrow * WMT;
    const int colBase = n0 + wcol * WNT;
    #pragma unroll
    for (int fm = 0; fm < MF; fm++) {
        #pragma unroll
        for (int fn = 0; fn < NF; fn++) {
            const int c = colBase + fn * 8 + tig * 2;
            float v0 = acc[fm][fn][0], v1 = acc[fm][fn][1];
            float v2 = acc[fm][fn][2], v3 = acc[fm][fn][3];
            if constexpr (MODE <= 2) {
                const float b0 = bias[c], b1 = bias[c + 1];
                v0 += b0; v1 += b1; v2 += b0; v3 += b1;
            }
            if constexpr (MODE == 1) {
                v0 = fmaxf(v0, 0.f); v1 = fmaxf(v1, 0.f);
                v2 = fmaxf(v2, 0.f); v3 = fmaxf(v3, 0.f);
            }
            if constexpr (MODE == 3) {
                v0 *= 0.125f; v1 *= 0.125f; v2 *= 0.125f; v3 *= 0.125f;
            }
            const int r0 = rowBase + fm * 16 + g;
            const int r1 = r0 + 8;
            if constexpr (MODE == 0 || MODE == 1) {
                *(float2*)(C + (size_t)r0 * 1024 + c) = make_float2(v0, v1);
                *(float2*)(C + (size_t)r1 * 1024 + c) = make_float2(v2, v3);
            } else if constexpr (MODE == 3) {
                float* Cz = C + (size_t)z * (1024u * 1024u);
                *(float2*)(Cz + (size_t)r0 * 1024 + c) = make_float2(v0, v1);
                *(float2*)(Cz + (size_t)r1 * 1024 + c) = make_float2(v2, v3);
            } else if constexpr (MODE == 2) {
                const int h0 = c & 15, d0 = c >> 4;
                const int h1 = (c + 1) & 15, d1 = (c + 1) >> 4;
                { const int b = r0 >> 10, i = r0 & 1023;
                  C[((size_t)(b * 16 + h0) * 1024 + i) * 64 + d0] = v0;
                  C[((size_t)(b * 16 + h1) * 1024 + i) * 64 + d1] = v1; }
                { const int b = r1 >> 10, i = r1 & 1023;
                  C[((size_t)(b * 16 + h0) * 1024 + i) * 64 + d0] = v2;
                  C[((size_t)(b * 16 + h1) * 1024 + i) * 64 + d1] = v3; }
            } else { // MODE 4
                const int b = z >> 4, h = z & 15;
                float* base0 = C + ((size_t)(b * 1024 + r0)) * 1024;
                float* base1 = C + ((size_t)(b * 1024 + r1)) * 1024;
                base0[c * 16 + h]       = v0;
                base0[(c + 1) * 16 + h] = v1;
                base1[c * 16 + h]       = v2;
                base1[(c + 1) * 16 + h] = v3;
            }
        }
    }
}

// ---------------------------------------------------------------------------
// Row softmax over j, then p += mask1 (+ mask2).  In-place on S.
// ---------------------------------------------------------------------------
__global__ void softmax_mask_k(float* __restrict__ S,
                               const float* __restrict__ m1,
                               const float* __restrict__ m2)
{
    __shared__ float red[256];
    const int r   = blockIdx.x;          // bh*SEQ + i
    const int bh  = r >> 10;
    const int i   = r & 1023;
    const int b   = bh >> 4;
    const int tid = threadIdx.x;

    float* row = S + (size_t)r * SEQ;
    const float* mr1 = m1 + ((size_t)b * SEQ + i) * SEQ;
    const float* mr2 = m2 ? m2 + ((size_t)b * SEQ + i) * SEQ : nullptr;

    float v[4];
    #pragma unroll
    for (int c = 0; c < 4; c++) v[c] = row[tid + c*256];

    float mx = fmaxf(fmaxf(v[0], v[1]), fmaxf(v[2], v[3]));
    red[tid] = mx; __syncthreads();
    for (int s = 128; s > 0; s >>= 1) {
        if (tid < s) red[tid] = fmaxf(red[tid], red[tid + s]);
        __syncthreads();
    }
    mx = red[0]; __syncthreads();

    float e[4], sum = 0.f;
    #pragma unroll
    for (int c = 0; c < 4; c++) { e[c] = expf(v[c] - mx); sum += e[c]; }
    red[tid] = sum; __syncthreads();
    for (int s = 128; s > 0; s >>= 1) {
        if (tid < s) red[tid] += red[tid + s];
        __syncthreads();
    }
    const float inv = 1.f / red[0];

    #pragma unroll
    for (int c = 0; c < 4; c++) {
        const int j = tid + c*256;
        float p = e[c] * inv + mr1[j];
        if (mr2) p += mr2[j];
        row[j] = p;
    }
}

// ---------------------------------------------------------------------------
// out = LayerNorm(X_row)*g + b + res_row   (eps 1e-5, over EMB=1024)
// ---------------------------------------------------------------------------
__global__ void ln_res_k(const float* __restrict__ X,
                         const float* __restrict__ res,
                         const float* __restrict__ gam,
                         const float* __restrict__ bet,
                         float* __restrict__ out)
{
    __shared__ float red[256];
    const int r   = blockIdx.x;
    const int tid = threadIdx.x;
    const float* xr = X   + (size_t)r * EMB;
    const float* rr = res + (size_t)r * EMB;
    float* orow     = out + (size_t)r * EMB;

    float v[4];
    #pragma unroll
    for (int c = 0; c < 4; c++) v[c] = xr[tid + c*256];

    float s = v[0] + v[1] + v[2] + v[3];
    red[tid] = s; __syncthreads();
    for (int k = 128; k > 0; k >>= 1) {
        if (tid < k) red[tid] += red[tid + k];
        __syncthreads();
    }
    const float mean = red[0] * (1.f / EMB); __syncthreads();

    float sq = 0.f;
    #pragma unroll
    for (int c = 0; c < 4; c++) { float d = v[c] - mean; sq += d * d; }
    red[tid] = sq; __syncthreads();
    for (int k = 128; k > 0; k >>= 1) {
        if (tid < k) red[tid] += red[tid + k];
        __syncthreads();
    }
    const float rstd = rsqrtf(red[0] * (1.f / EMB) + 1e-5f);

    #pragma unroll
    for (int c = 0; c < 4; c++) {
        const int j = tid + c*256;
        orow[j] = (v[c] - mean) * rstd * gam[j] + bet[j] + rr[j];
    }
}

// ---------------------------------------------------------------------------
extern "C" void kernel_launch(void* const* d_in, const int* in_sizes, int n_in,
                              void* d_out, int out_size)
{
    (void)in_sizes; (void)n_in; (void)out_size;

    const float* x      = (const float*)d_in[0];
    const float* ctx    = (const float*)d_in[1];
    const float* causal = (const float*)d_in[2];
    const float* ppad   = (const float*)d_in[3];
    const float* cpad   = (const float*)d_in[4];
    const float* sa_Wq  = (const float*)d_in[5];
    const float* sa_bq  = (const float*)d_in[6];
    const float* sa_Wk  = (const float*)d_in[7];
    const float* sa_bk  = (const float*)d_in[8];
    const float* sa_Wv  = (const float*)d_in[9];
    const float* sa_bv  = (const float*)d_in[10];
    const float* ca_Wq  = (const float*)d_in[11];
    const float* ca_bq  = (const float*)d_in[12];
    const float* ca_Wk  = (const float*)d_in[13];
    const float* ca_bk  = (const float*)d_in[14];
    const float* ca_Wv  = (const float*)d_in[15];
    const float* ca_bv  = (const float*)d_in[16];
    const float* ln1_g  = (const float*)d_in[17];
    const float* ln1_b  = (const float*)d_in[18];
    const float* ln2_g  = (const float*)d_in[19];
    const float* ln2_b  = (const float*)d_in[20];
    const float* ln3_g  = (const float*)d_in[21];
    const float* ln3_b  = (const float*)d_in[22];
    const float* mlp_W1 = (const float*)d_in[23];
    const float* mlp_b1 = (const float*)d_in[24];
    const float* mlp_W2 = (const float*)d_in[25];
    const float* mlp_b2 = (const float*)d_in[26];
    float* out = (float*)d_out;

    float *Qh, *Kh, *Vh, *S, *tmp, *x1, *x2, *hid;
    cudaGetSymbolAddress((void**)&Qh,  g_Qh);
    cudaGetSymbolAddress((void**)&Kh,  g_Kh);
    cudaGetSymbolAddress((void**)&Vh,  g_Vh);
    cudaGetSymbolAddress((void**)&S,   g_S);
    cudaGetSymbolAddress((void**)&tmp, g_tmp);
    cudaGetSymbolAddress((void**)&x1,  g_x1);
    cudaGetSymbolAddress((void**)&x2,  g_x2);
    cudaGetSymbolAddress((void**)&hid, g_hid);

    constexpr int SMEM128 = (2*32*(128+8) + 2*32*(128+8)) * 4;  // 69632
    constexpr int SMEM64  = (2*32*(128+8) + 2*32*( 64+8)) * 4;  // 53248

    auto kScatter = tf32gemm<128, 2, 4, false, 2>;  // projections -> head-major
    auto kRelu    = tf32gemm<128, 2, 4, false, 1>;  // mlp1
    auto kPlain   = tf32gemm<128, 2, 4, false, 0>;  // mlp2
    auto kQK      = tf32gemm<128, 2, 4, true,  3>;  // scores
    auto kPV      = tf32gemm< 64, 4, 2, false, 4>;  // P@V interleave

    cudaFuncSetAttribute(kScatter, cudaFuncAttributeMaxDynamicSharedMemorySize, SMEM128);
    cudaFuncSetAttribute(kRelu,    cudaFuncAttributeMaxDynamicSharedMemorySize, SMEM128);
    cudaFuncSetAttribute(kPlain,   cudaFuncAttributeMaxDynamicSharedMemorySize, SMEM128);
    cudaFuncSetAttribute(kQK,      cudaFuncAttributeMaxDynamicSharedMemorySize, SMEM128);
    cudaFuncSetAttribute(kPV,      cudaFuncAttributeMaxDynamicSharedMemorySize, SMEM64);

    const dim3 gProj(EMB/128, NROWS/128, 1);        // (8, 16)
    const dim3 gQK(SEQ/128, SEQ/128, NB*NHD);       // (8, 8, 32)
    const dim3 gPV(1, SEQ/128, NB*NHD);             // (1, 8, 32)
    const size_t hs = (size_t)SEQ * HDD;            // 65536
    const size_t ss = (size_t)SEQ * SEQ;            // 1048576

    // ---- self-attention ----
    kScatter<<<gProj, 256, SMEM128>>>(x, sa_Wq, sa_bq, Qh, EMB, EMB, EMB, 0, 0);
    kScatter<<<gProj, 256, SMEM128>>>(x, sa_Wk, sa_bk, Kh, EMB, EMB, EMB, 0, 0);
    kScatter<<<gProj, 256, SMEM128>>>(x, sa_Wv, sa_bv, Vh, EMB, EMB, EMB, 0, 0);
    kQK<<<gQK, 256, SMEM128>>>(Qh, Kh, nullptr, S, HDD, HDD, HDD, hs, hs);
    softmax_mask_k<<<NB*NHD*SEQ, 256>>>(S, causal, ppad);
    kPV<<<gPV, 256, SMEM64>>>(S, Vh, nullptr, tmp, SEQ, SEQ, HDD, ss, hs);
    ln_res_k<<<NROWS, 256>>>(tmp, x, ln1_g, ln1_b, x1);

    // ---- cross-attention ----
    kScatter<<<gProj, 256, SMEM128>>>(x1,  ca_Wq, ca_bq, Qh, EMB, EMB, EMB, 0, 0);
    kScatter<<<gProj, 256, SMEM128>>>(ctx, ca_Wk, ca_bk, Kh, EMB, EMB, EMB, 0, 0);
    kScatter<<<gProj, 256, SMEM128>>>(ctx, ca_Wv, ca_bv, Vh, EMB, EMB, EMB, 0, 0);
    kQK<<<gQK, 256, SMEM128>>>(Qh, Kh, nullptr, S, HDD, HDD, HDD, hs, hs);
    softmax_mask_k<<<NB*NHD*SEQ, 256>>>(S, cpad, nullptr);
    kPV<<<gPV, 256, SMEM64>>>(S, Vh, nullptr, tmp, SEQ, SEQ, HDD, ss, hs);
    ln_res_k<<<NROWS, 256>>>(tmp, x1, ln2_g, ln2_b, x2);

    // ---- MLP ----
    kRelu <<<gProj, 256, SMEM128>>>(x2,  mlp_W1, mlp_b1, hid, EMB, EMB, EMB, 0, 0);
    kPlain<<<gProj, 256, SMEM128>>>(hid, mlp_W2, mlp_b2, tmp, EMB, EMB, EMB, 0, 0);
    ln_res_k<<<NROWS, 256>>>(tmp, x2, ln3_g, ln3_b, out);
}

// round 6
// speedup vs baseline: 2.5345x; 1.3827x over previous
#include <cuda_runtime.h>
#include <math.h>
#include <stdint.h>

#define NB   2
#define SEQ  1024
#define EMB  1024
#define NHD  16
#define HDD  64
#define NROWS (NB*SEQ)      // 2048

// ---------------- scratch (device globals) ----------------------------------
__device__ float g_cvt[12*1024*1024];   // 48MB: 8 weights (1M ea) + xt(2M) + ctxt(2M)
__device__ float g_Qh [NB*NHD*SEQ*HDD]; // [bh][i][d]
__device__ float g_Kt [NB*NHD*HDD*SEQ]; // [bh][d][j]  (transposed K)
__device__ float g_Vh [NB*NHD*SEQ*HDD]; // [bh][j][o]
__device__ float g_S  [NB*NHD*SEQ*SEQ]; // 128MB scores/probs
__device__ float g_tmp[NROWS*EMB];
__device__ float g_x1 [NROWS*EMB];
__device__ float g_x2 [NROWS*EMB];
__device__ float g_x1t[NROWS*EMB];
__device__ float g_x2t[NROWS*EMB];
__device__ float g_hid[NROWS*EMB];

__device__ __forceinline__ float cvt_tf32(float x) {
    uint32_t u;
    asm("cvt.rna.tf32.f32 %0, %1;" : "=r"(u) : "f"(x));
    return __uint_as_float(u);
}

__device__ __forceinline__ void mma_tf32(float* d,
                                         const uint32_t* a, const uint32_t* b) {
    asm volatile(
        "mma.sync.aligned.m16n8k8.row.col.f32.tf32.tf32.f32 "
        "{%0,%1,%2,%3}, {%4,%5,%6,%7}, {%8,%9}, {%0,%1,%2,%3};"
        : "+f"(d[0]), "+f"(d[1]), "+f"(d[2]), "+f"(d[3])
        : "r"(a[0]), "r"(a[1]), "r"(a[2]), "r"(a[3]), "r"(b[0]), "r"(b[1]));
}

// ---------------------------------------------------------------------------
// One-shot tf32 rounding pass: 8 weight matrices + x + ctx -> g_cvt.
// 12M floats = 3,145,728 float4. seg = i>>18 (256K float4 per 1M floats).
// ---------------------------------------------------------------------------
struct CvtPtrs { const float4* p[12]; };

__global__ void cvt_all_k(CvtPtrs ptrs, float4* __restrict__ dst)
{
    int i = blockIdx.x * blockDim.x + threadIdx.x;
    if (i >= 12 * 262144) return;
    int seg = i >> 18;
    int off = i & 0x3FFFF;
    float4 v = ptrs.p[seg][off];
    float4 w;
    w.x = cvt_tf32(v.x); w.y = cvt_tf32(v.y);
    w.z = cvt_tf32(v.z); w.w = cvt_tf32(v.w);
    dst[i] = w;
}

// ---------------------------------------------------------------------------
// tf32 GEMM, 128x64x32 tile, 4 warps of 64x32, 4-stage cp.async pipeline.
// A: [M,K] row-major (lda), already tf32-rounded.  B: [K,N] row-major (ldb),
// already tf32-rounded.  Per-z strides for batched (attention) use.
// MODE 0: C[r*1024+c] = acc + bias[c]                       (fp32)
// MODE 1: relu(acc+bias) rounded to tf32                    (hid)
// MODE 2: head-scatter rounded: Qh/Vh[((b*16+h)*1024+i)*64+d]
// MODE 3: scores: C[z*1M + r*1024 + c] = acc*0.125          (fp32)
// MODE 4: pv interleave: C[(b*1024+r)*1024 + c*16 + h]      (fp32)
// MODE 5: K-transpose scatter rounded: Kt[((b*16+h)*64+d)*1024+i]
// ---------------------------------------------------------------------------
template<int MODE>
__global__ void __launch_bounds__(128, 2)
tf32gemm2(const float* __restrict__ A, const float* __restrict__ Bg,
          const float* __restrict__ bias, float* __restrict__ C,
          int K, int lda, int ldb, size_t astride, size_t bstride)
{
    constexpr int BM = 128, BN = 64, BK = 32, STG = 4;
    constexpr int AROW = BK + 4;    // 36 floats
    constexpr int BROW = BN + 8;    // 72 floats
    constexpr int ASTGF = BM * AROW;   // 4608 floats
    constexpr int BSTGF = BK * BROW;   // 2304 floats

    extern __shared__ float sm[];
    float* As = sm;
    float* Bs = sm + STG * ASTGF;
    const uint32_t sAb = (uint32_t)__cvta_generic_to_shared(As);
    const uint32_t sBb = (uint32_t)__cvta_generic_to_shared(Bs);

    const int tid  = threadIdx.x;
    const int lane = tid & 31;
    const int wid  = tid >> 5;
    const int g    = lane >> 2;
    const int tig  = lane & 3;
    const int wrow = wid >> 1;      // 0..1
    const int wcol = wid & 1;       // 0..1

    const int z  = blockIdx.z;
    const int m0 = blockIdx.y * BM;
    const int n0 = blockIdx.x * BN;
    const float* Ab = A  + (size_t)z * astride;
    const float* Bb = Bg + (size_t)z * bstride;

    float acc[4][4][4];
    #pragma unroll
    for (int i = 0; i < 4; i++)
        #pragma unroll
        for (int j = 0; j < 4; j++)
            #pragma unroll
            for (int q = 0; q < 4; q++) acc[i][j][q] = 0.f;

    auto load_stage = [&](int s, int k0) {
        #pragma unroll
        for (int i = 0; i < 8; i++) {             // A: 128 rows x 8 float4
            int q   = tid + i * 128;
            int row = q >> 3, kq = (q & 7) << 2;
            const float* src = Ab + (size_t)(m0 + row) * lda + k0 + kq;
            uint32_t dst = sAb + (uint32_t)((s * ASTGF + row * AROW + kq) * 4);
            asm volatile("cp.async.cg.shared.global [%0], [%1], 16;"
                         :: "r"(dst), "l"(src));
        }
        #pragma unroll
        for (int i = 0; i < 4; i++) {             // B: 32 rows x 16 float4
            int q   = tid + i * 128;
            int row = q >> 4, nq = (q & 15) << 2;
            const float* src = Bb + (size_t)(k0 + row) * ldb + n0 + nq;
            uint32_t dst = sBb + (uint32_t)((s * BSTGF + row * BROW + nq) * 4);
            asm volatile("cp.async.cg.shared.global [%0], [%1], 16;"
                         :: "r"(dst), "l"(src));
        }
    };

    const int KT = K >> 5;
    #pragma unroll
    for (int s = 0; s < STG - 1; s++) {
        if (s < KT) load_stage(s, s * BK);
        asm volatile("cp.async.commit_group;");
    }

    for (int kt = 0; kt < KT; kt++) {
        asm volatile("cp.async.wait_group 2;");
        __syncthreads();
        {
            int nk = kt + STG - 1;
            if (nk < KT) load_stage(nk & 3, nk * BK);
            asm volatile("cp.async.commit_group;");
        }
        const float* As_ = As + (kt & 3) * ASTGF + (wrow * 64 + g) * AROW;
        const float* Bs_ = Bs + (kt & 3) * BSTGF + wcol * 32 + g;
        #pragma unroll
        for (int ks = 0; ks < 4; ks++) {
            const int kk = ks * 8 + tig;
            uint32_t a[4][4], b[4][2];
            #pragma unroll
            for (int fm = 0; fm < 4; fm++) {
                const float* p = As_ + fm * 16 * AROW + kk;
                a[fm][0] = __float_as_uint(p[0]);
                a[fm][1] = __float_as_uint(p[8 * AROW]);
                a[fm][2] = __float_as_uint(p[4]);
                a[fm][3] = __float_as_uint(p[8 * AROW + 4]);
            }
            #pragma unroll
            for (int fn = 0; fn < 4; fn++) {
                const float* p = Bs_ + kk * BROW + fn * 8;
                b[fn][0] = __float_as_uint(p[0]);
                b[fn][1] = __float_as_uint(p[4 * BROW]);
            }
            #pragma unroll
            for (int fm = 0; fm < 4; fm++)
                #pragma unroll
                for (int fn = 0; fn < 4; fn++)
                    mma_tf32(acc[fm][fn], a[fm], b[fn]);
        }
        __syncthreads();
    }

    // ----------------------------- epilogue --------------------------------
    const int rowBase = m0 + wrow * 64;
    const int colBase = n0 + wcol * 32;
    #pragma unroll
    for (int fm = 0; fm < 4; fm++) {
        #pragma unroll
        for (int fn = 0; fn < 4; fn++) {
            const int c = colBase + fn * 8 + tig * 2;
            float v0 = acc[fm][fn][0], v1 = acc[fm][fn][1];
            float v2 = acc[fm][fn][2], v3 = acc[fm][fn][3];
            if constexpr (MODE == 0 || MODE == 1 || MODE == 2 || MODE == 5) {
                const float b0 = bias[c], b1 = bias[c + 1];
                v0 += b0; v1 += b1; v2 += b0; v3 += b1;
            }
            if constexpr (MODE == 1) {
                v0 = fmaxf(v0, 0.f); v1 = fmaxf(v1, 0.f);
                v2 = fmaxf(v2, 0.f); v3 = fmaxf(v3, 0.f);
            }
            if constexpr (MODE == 1 || MODE == 2 || MODE == 5) {
                v0 = cvt_tf32(v0); v1 = cvt_tf32(v1);
                v2 = cvt_tf32(v2); v3 = cvt_tf32(v3);
            }
            if constexpr (MODE == 3) {
                v0 *= 0.125f; v1 *= 0.125f; v2 *= 0.125f; v3 *= 0.125f;
            }
            const int r0 = rowBase + fm * 16 + g;
            const int r1 = r0 + 8;
            if constexpr (MODE == 0 || MODE == 1) {
                *(float2*)(C + (size_t)r0 * 1024 + c) = make_float2(v0, v1);
                *(float2*)(C + (size_t)r1 * 1024 + c) = make_float2(v2, v3);
            } else if constexpr (MODE == 3) {
                float* Cz = C + (size_t)z * (1024u * 1024u);
                *(float2*)(Cz + (size_t)r0 * 1024 + c) = make_float2(v0, v1);
                *(float2*)(Cz + (size_t)r1 * 1024 + c) = make_float2(v2, v3);
            } else if constexpr (MODE == 2) {
                const int h0 = c & 15, d0 = c >> 4;
                const int h1 = (c + 1) & 15, d1 = (c + 1) >> 4;
                { const int b = r0 >> 10, i = r0 & 1023;
                  C[((size_t)(b * 16 + h0) * 1024 + i) * 64 + d0] = v0;
                  C[((size_t)(b * 16 + h1) * 1024 + i) * 64 + d1] = v1; }
                { const int b = r1 >> 10, i = r1 & 1023;
                  C[((size_t)(b * 16 + h0) * 1024 + i) * 64 + d0] = v2;
                  C[((size_t)(b * 16 + h1) * 1024 + i) * 64 + d1] = v3; }
            } else if constexpr (MODE == 5) {
                const int h0 = c & 15, d0 = c >> 4;
                const int h1 = (c + 1) & 15, d1 = (c + 1) >> 4;
                { const int b = r0 >> 10, i = r0 & 1023;
                  C[((size_t)(b * 16 + h0) * 64 + d0) * 1024 + i] = v0;
                  C[((size_t)(b * 16 + h1) * 64 + d1) * 1024 + i] = v1; }
                { const int b = r1 >> 10, i = r1 & 1023;
                  C[((size_t)(b * 16 + h0) * 64 + d0) * 1024 + i] = v2;
                  C[((size_t)(b * 16 + h1) * 64 + d1) * 1024 + i] = v3; }
            } else { // MODE 4
                const int b = z >> 4, h = z & 15;
                float* base0 = C + ((size_t)(b * 1024 + r0)) * 1024;
                float* base1 = C + ((size_t)(b * 1024 + r1)) * 1024;
                base0[c * 16 + h]       = v0;
                base0[(c + 1) * 16 + h] = v1;
                base1[c * 16 + h]       = v2;
                base1[(c + 1) * 16 + h] = v3;
            }
        }
    }
}

// ---------------------------------------------------------------------------
// Row softmax over j, then p += mask1 (+mask2); writes tf32-rounded P.
// ---------------------------------------------------------------------------
__global__ void softmax_mask_k(float* __restrict__ S,
                               const float* __restrict__ m1,
                               const float* __restrict__ m2)
{
    __shared__ float red[256];
    const int r   = blockIdx.x;
    const int bh  = r >> 10;
    const int i   = r & 1023;
    const int b   = bh >> 4;
    const int tid = threadIdx.x;

    float* row = S + (size_t)r * SEQ;
    const float* mr1 = m1 + ((size_t)b * SEQ + i) * SEQ;
    const float* mr2 = m2 ? m2 + ((size_t)b * SEQ + i) * SEQ : nullptr;

    float v[4];
    #pragma unroll
    for (int c = 0; c < 4; c++) v[c] = row[tid + c*256];

    float mx = fmaxf(fmaxf(v[0], v[1]), fmaxf(v[2], v[3]));
    red[tid] = mx; __syncthreads();
    for (int s = 128; s > 0; s >>= 1) {
        if (tid < s) red[tid] = fmaxf(red[tid], red[tid + s]);
        __syncthreads();
    }
    mx = red[0]; __syncthreads();

    float e[4], sum = 0.f;
    #pragma unroll
    for (int c = 0; c < 4; c++) { e[c] = expf(v[c] - mx); sum += e[c]; }
    red[tid] = sum; __syncthreads();
    for (int s = 128; s > 0; s >>= 1) {
        if (tid < s) red[tid] += red[tid + s];
        __syncthreads();
    }
    const float inv = 1.f / red[0];

    #pragma unroll
    for (int c = 0; c < 4; c++) {
        const int j = tid + c*256;
        float p = e[c] * inv + mr1[j];
        if (mr2) p += mr2[j];
        row[j] = cvt_tf32(p);
    }
}

// ---------------------------------------------------------------------------
// out = LN(X)*g + b + res; optional tf32-rounded copy for downstream GEMMs.
// ---------------------------------------------------------------------------
__global__ void ln_res_k(const float* __restrict__ X,
                         const float* __restrict__ res,
                         const float* __restrict__ gam,
                         const float* __restrict__ bet,
                         float* __restrict__ out,
                         float* __restrict__ out_t)
{
    __shared__ float red[256];
    const int r   = blockIdx.x;
    const int tid = threadIdx.x;
    const float* xr = X   + (size_t)r * EMB;
    const float* rr = res + (size_t)r * EMB;
    float* orow     = out + (size_t)r * EMB;

    float v[4];
    #pragma unroll
    for (int c = 0; c < 4; c++) v[c] = xr[tid + c*256];

    float s = v[0] + v[1] + v[2] + v[3];
    red[tid] = s; __syncthreads();
    for (int k = 128; k > 0; k >>= 1) {
        if (tid < k) red[tid] += red[tid + k];
        __syncthreads();
    }
    const float mean = red[0] * (1.f / EMB); __syncthreads();

    float sq = 0.f;
    #pragma unroll
    for (int c = 0; c < 4; c++) { float d = v[c] - mean; sq += d * d; }
    red[tid] = sq; __syncthreads();
    for (int k = 128; k > 0; k >>= 1) {
        if (tid < k) red[tid] += red[tid + k];
        __syncthreads();
    }
    const float rstd = rsqrtf(red[0] * (1.f / EMB) + 1e-5f);

    #pragma unroll
    for (int c = 0; c < 4; c++) {
        const int j = tid + c*256;
        float o = (v[c] - mean) * rstd * gam[j] + bet[j] + rr[j];
        orow[j] = o;
        if (out_t) out_t[(size_t)r * EMB + j] = cvt_tf32(o);
    }
}

// ---------------------------------------------------------------------------
extern "C" void kernel_launch(void* const* d_in, const int* in_sizes, int n_in,
                              void* d_out, int out_size)
{
    (void)in_sizes; (void)n_in; (void)out_size;

    const float* x      = (const float*)d_in[0];
    const float* ctx    = (const float*)d_in[1];
    const float* causal = (const float*)d_in[2];
    const float* ppad   = (const float*)d_in[3];
    const float* cpad   = (const float*)d_in[4];
    const float* sa_Wq  = (const float*)d_in[5];
    const float* sa_bq  = (const float*)d_in[6];
    const float* sa_Wk  = (const float*)d_in[7];
    const float* sa_bk  = (const float*)d_in[8];
    const float* sa_Wv  = (const float*)d_in[9];
    const float* sa_bv  = (const float*)d_in[10];
    const float* ca_Wq  = (const float*)d_in[11];
    const float* ca_bq  = (const float*)d_in[12];
    const float* ca_Wk  = (const float*)d_in[13];
    const float* ca_bk  = (const float*)d_in[14];
    const float* ca_Wv  = (const float*)d_in[15];
    const float* ca_bv  = (const float*)d_in[16];
    const float* ln1_g  = (const float*)d_in[17];
    const float* ln1_b  = (const float*)d_in[18];
    const float* ln2_g  = (const float*)d_in[19];
    const float* ln2_b  = (const float*)d_in[20];
    const float* ln3_g  = (const float*)d_in[21];
    const float* ln3_b  = (const float*)d_in[22];
    const float* mlp_W1 = (const float*)d_in[23];
    const float* mlp_b1 = (const float*)d_in[24];
    const float* mlp_W2 = (const float*)d_in[25];
    const float* mlp_b2 = (const float*)d_in[26];
    float* out = (float*)d_out;

    float *cvt, *Qh, *Kt, *Vh, *S, *tmp, *x1, *x2, *x1t, *x2t, *hid;
    cudaGetSymbolAddress((void**)&cvt, g_cvt);
    cudaGetSymbolAddress((void**)&Qh,  g_Qh);
    cudaGetSymbolAddress((void**)&Kt,  g_Kt);
    cudaGetSymbolAddress((void**)&Vh,  g_Vh);
    cudaGetSymbolAddress((void**)&S,   g_S);
    cudaGetSymbolAddress((void**)&tmp, g_tmp);
    cudaGetSymbolAddress((void**)&x1,  g_x1);
    cudaGetSymbolAddress((void**)&x2,  g_x2);
    cudaGetSymbolAddress((void**)&x1t, g_x1t);
    cudaGetSymbolAddress((void**)&x2t, g_x2t);
    cudaGetSymbolAddress((void**)&hid, g_hid);

    const float* WT[8] = { cvt + 0*1048576, cvt + 1*1048576, cvt + 2*1048576,
                           cvt + 3*1048576, cvt + 4*1048576, cvt + 5*1048576,
                           cvt + 6*1048576, cvt + 7*1048576 };
    const float* XT  = cvt + 8*1048576;
    const float* CTT = cvt + 10*1048576;

    constexpr int SMEM = (4*128*36 + 4*32*72) * 4;   // 110592 bytes

    auto kPlain   = tf32gemm2<0>;
    auto kRelu    = tf32gemm2<1>;
    auto kScatter = tf32gemm2<2>;
    auto kQK      = tf32gemm2<3>;
    auto kPV      = tf32gemm2<4>;
    auto kKT      = tf32gemm2<5>;
    cudaFuncSetAttribute(kPlain,   cudaFuncAttributeMaxDynamicSharedMemorySize, SMEM);
    cudaFuncSetAttribute(kRelu,    cudaFuncAttributeMaxDynamicSharedMemorySize, SMEM);
    cudaFuncSetAttribute(kScatter, cudaFuncAttributeMaxDynamicSharedMemorySize, SMEM);
    cudaFuncSetAttribute(kQK,      cudaFuncAttributeMaxDynamicSharedMemorySize, SMEM);
    cudaFuncSetAttribute(kPV,      cudaFuncAttributeMaxDynamicSharedMemorySize, SMEM);
    cudaFuncSetAttribute(kKT,      cudaFuncAttributeMaxDynamicSharedMemorySize, SMEM);

    // ---- 0. one-shot tf32 rounding pass ----
    CvtPtrs cp;
    cp.p[0] = (const float4*)sa_Wq;  cp.p[1] = (const float4*)sa_Wk;
    cp.p[2] = (const float4*)sa_Wv;  cp.p[3] = (const float4*)ca_Wq;
    cp.p[4] = (const float4*)ca_Wk;  cp.p[5] = (const float4*)ca_Wv;
    cp.p[6] = (const float4*)mlp_W1; cp.p[7] = (const float4*)mlp_W2;
    cp.p[8]  = (const float4*)x;            cp.p[9]  = (const float4*)(x + 4*262144);
    cp.p[10] = (const float4*)ctx;          cp.p[11] = (const float4*)(ctx + 4*262144);
    cvt_all_k<<<12288, 256>>>(cp, (float4*)cvt);

    const dim3 gProj(EMB/64, NROWS/128, 1);       // (16, 16)
    const dim3 gQK(SEQ/64, SEQ/128, NB*NHD);      // (16, 8, 32)
    const dim3 gPV(1, SEQ/128, NB*NHD);           // (1, 8, 32)
    const size_t hs = (size_t)SEQ * HDD;          // 65536
    const size_t ss = (size_t)SEQ * SEQ;          // 1048576

    // ---- self-attention ----
    kScatter<<<gProj, 128, SMEM>>>(XT, WT[0], sa_bq, Qh, EMB, EMB, EMB, 0, 0);
    kKT     <<<gProj, 128, SMEM>>>(XT, WT[1], sa_bk, Kt, EMB, EMB, EMB, 0, 0);
    kScatter<<<gProj, 128, SMEM>>>(XT, WT[2], sa_bv, Vh, EMB, EMB, EMB, 0, 0);
    kQK<<<gQK, 128, SMEM>>>(Qh, Kt, nullptr, S, HDD, HDD, SEQ, hs, hs);
    softmax_mask_k<<<NB*NHD*SEQ, 256>>>(S, causal, ppad);
    kPV<<<gPV, 128, SMEM>>>(S, Vh, nullptr, tmp, SEQ, SEQ, HDD, ss, hs);
    ln_res_k<<<NROWS, 256>>>(tmp, x, ln1_g, ln1_b, x1, x1t);

    // ---- cross-attention ----
    kScatter<<<gProj, 128, SMEM>>>(x1t, WT[3], ca_bq, Qh, EMB, EMB, EMB, 0, 0);
    kKT     <<<gProj, 128, SMEM>>>(CTT, WT[4], ca_bk, Kt, EMB, EMB, EMB, 0, 0);
    kScatter<<<gProj, 128, SMEM>>>(CTT, WT[5], ca_bv, Vh, EMB, EMB, EMB, 0, 0);
    kQK<<<gQK, 128, SMEM>>>(Qh, Kt, nullptr, S, HDD, HDD, SEQ, hs, hs);
    softmax_mask_k<<<NB*NHD*SEQ, 256>>>(S, cpad, nullptr);
    kPV<<<gPV, 128, SMEM>>>(S, Vh, nullptr, tmp, SEQ, SEQ, HDD, ss, hs);
    ln_res_k<<<NROWS, 256>>>(tmp, x1, ln2_g, ln2_b, x2, x2t);

    // ---- MLP ----
    kRelu <<<gProj, 128, SMEM>>>(x2t, WT[6], mlp_b1, hid, EMB, EMB, EMB, 0, 0);
    kPlain<<<gProj, 128, SMEM>>>(hid, WT[7], mlp_b2, tmp, EMB, EMB, EMB, 0, 0);
    ln_res_k<<<NROWS, 256>>>(tmp, x2, ln3_g, ln3_b, out, nullptr);
}